// round 1
// baseline (speedup 1.0000x reference)
#include <cuda_runtime.h>
#include <cuda_fp16.h>
#include <cstdint>
#include <cstddef>

#define T_TOK 4096
#define DMODEL 1024
#define FDIM 768
#define NEXP 64
#define TOPK 8
#define TK 32768          // T_TOK * TOPK
#define MAXT 320          // upper bound on row tiles: 32768/128 + 64

// ---------------- scratch (static device globals; no allocation) ----------------
__device__ __align__(16) __half g_Xh[(size_t)T_TOK * DMODEL];
__device__ __align__(16) __half g_Wg[(size_t)NEXP * FDIM * DMODEL];
__device__ __align__(16) __half g_Wu[(size_t)NEXP * FDIM * DMODEL];
__device__ __align__(16) __half g_Wd[(size_t)NEXP * DMODEL * FDIM];
__device__ __align__(16) __half g_H[(size_t)(TK + 128) * FDIM];   // padded rows
__device__ __align__(16) float  g_O2[(size_t)TK * DMODEL];

__device__ int   g_ids[TK];
__device__ float g_w[TK];
__device__ int   g_counts[NEXP];
__device__ int   g_cursor[NEXP];
__device__ int   g_off[NEXP + 1];
__device__ int   g_toff[NEXP + 1];
__device__ int   g_row2tok[TK + 128];
__device__ int   g_slot2row[TK];
__device__ int   g_ntiles[1];

// ---------------- helpers ----------------
__device__ __forceinline__ void mma16816(float* c, const uint32_t* a, const uint32_t* b) {
    asm volatile(
        "mma.sync.aligned.m16n8k16.row.col.f32.f16.f16.f32 "
        "{%0,%1,%2,%3}, {%4,%5,%6,%7}, {%8,%9}, {%0,%1,%2,%3};\n"
        : "+f"(c[0]), "+f"(c[1]), "+f"(c[2]), "+f"(c[3])
        : "r"(a[0]), "r"(a[1]), "r"(a[2]), "r"(a[3]), "r"(b[0]), "r"(b[1]));
}

__device__ __forceinline__ void cp16(void* dst, const void* src) {
    uint32_t d = (uint32_t)__cvta_generic_to_shared(dst);
    asm volatile("cp.async.ca.shared.global [%0], [%1], 16;\n" :: "r"(d), "l"(src));
}
__device__ __forceinline__ void cp_commit() {
    asm volatile("cp.async.commit_group;\n" ::: "memory");
}

// ---------------- kernels ----------------
__global__ void k_reset() {
    int t = threadIdx.x;
    if (t < NEXP) g_counts[t] = 0;
    if (t < 128) g_row2tok[TK + t] = 0;
}

__global__ void k_cvt(const float* __restrict__ s, int which, size_t n) {
    size_t i = ((size_t)blockIdx.x * blockDim.x + threadIdx.x) * 4;
    if (i >= n) return;
    __half* d = (which == 0) ? g_Xh : (which == 1) ? g_Wg : (which == 2) ? g_Wu : g_Wd;
    float4 v = *(const float4*)(s + i);
    *(__half2*)(d + i)     = __floats2half2_rn(v.x, v.y);
    *(__half2*)(d + i + 2) = __floats2half2_rn(v.z, v.w);
}

// Router: 4 tokens per block, 64 threads per token (one expert each).
__global__ void k_router(const float* __restrict__ x, const float* __restrict__ gw) {
    __shared__ float sx[4][DMODEL];
    __shared__ float slog[4][NEXP];
    int t0 = blockIdx.x * 4;
    for (int i = threadIdx.x; i < 4 * DMODEL; i += 256) {
        int tl = i >> 10;
        sx[tl][i & 1023] = x[(size_t)(t0 + tl) * DMODEL + (i & 1023)];
    }
    __syncthreads();
    int tl = threadIdx.x >> 6, e = threadIdx.x & 63;
    const float4* w4 = (const float4*)(gw + (size_t)e * DMODEL);
    const float4* x4 = (const float4*)sx[tl];
    float s = 0.f;
    #pragma unroll 8
    for (int k = 0; k < DMODEL / 4; k++) {
        float4 a = x4[k], b = w4[k];
        s += a.x * b.x + a.y * b.y + a.z * b.z + a.w * b.w;
    }
    slog[tl][e] = s;
    __syncthreads();
    if (threadIdx.x < 4) {
        int t = t0 + threadIdx.x;
        float* lg = slog[threadIdx.x];
        float mx = -1e30f;
        for (int i = 0; i < NEXP; i++) mx = fmaxf(mx, lg[i]);
        float p[NEXP]; float sum = 0.f;
        for (int i = 0; i < NEXP; i++) { p[i] = __expf(lg[i] - mx); sum += p[i]; }
        float inv = 1.f / sum;
        float wsum = 0.f;
        for (int k = 0; k < TOPK; k++) {
            float best = -1.f; int bi = 0;
            for (int i = 0; i < NEXP; i++) if (p[i] > best) { best = p[i]; bi = i; }
            p[bi] = -2.f;
            float wv = best * inv;
            g_w[t * TOPK + k] = wv;
            g_ids[t * TOPK + k] = bi;
            wsum += wv;
            atomicAdd(&g_counts[bi], 1);
        }
        float rn = 1.f / (wsum + 1e-20f);
        for (int k = 0; k < TOPK; k++) g_w[t * TOPK + k] *= rn;
    }
}

__global__ void k_scan() {
    if (threadIdx.x < NEXP) g_cursor[threadIdx.x] = 0;
    if (threadIdx.x == 0) {
        int off = 0, toff = 0;
        for (int e = 0; e < NEXP; e++) {
            g_off[e] = off; g_toff[e] = toff;
            off += g_counts[e];
            toff += (g_counts[e] + 127) >> 7;
        }
        g_off[NEXP] = off; g_toff[NEXP] = toff;
        g_ntiles[0] = toff;
    }
}

__global__ void k_scatter() {
    int i = blockIdx.x * 256 + threadIdx.x;
    if (i >= TK) return;
    int e = g_ids[i];
    int p = g_off[e] + atomicAdd(&g_cursor[e], 1);
    g_row2tok[p] = i >> 3;
    g_slot2row[i] = p;
}

// GEMM1 + fused SwiGLU: H[rows, F] = silu(A Wg^T) * (A Wu^T), grouped by expert.
// Tile: 128 rows x 64 F-cols, BK=64, 2-stage cp.async, 8 warps (4x2).
__global__ __launch_bounds__(256) void k_gemm1() {
    extern __shared__ __half smem[];
    const int SA = 80;
    __half* As[2]; __half* Gs[2]; __half* Us[2];
    As[0] = smem;                Gs[0] = As[0] + 128 * SA;  Us[0] = Gs[0] + 64 * SA;
    As[1] = Us[0] + 64 * SA;     Gs[1] = As[1] + 128 * SA;  Us[1] = Gs[1] + 64 * SA;

    int bx = blockIdx.x;
    if (bx >= g_ntiles[0]) return;

    __shared__ int s_e, s_m0, s_valid;
    __shared__ int stok[128];
    int tid = threadIdx.x;
    if (tid == 0) {
        int e = 0;
        while (!(bx >= g_toff[e] && bx < g_toff[e + 1])) e++;
        int lt = bx - g_toff[e];
        s_e = e;
        s_m0 = g_off[e] + lt * 128;
        int cnt = g_off[e + 1] - g_off[e];
        s_valid = min(128, cnt - lt * 128);
    }
    __syncthreads();
    int e = s_e, m0 = s_m0;
    if (tid < 128) stok[tid] = g_row2tok[m0 + tid];
    __syncthreads();

    int f0 = blockIdx.y * 64;
    int arow = tid >> 1;
    int acol = (tid & 1) * 32;                      // halves offset within 64-wide k chunk
    const __half* axsrc = g_Xh + (size_t)stok[arow] * DMODEL + acol;
    int wmat = tid >> 7;
    int wrow = (tid & 127) >> 1;
    const __half* wsrc = (wmat ? g_Wu : g_Wg) + ((size_t)e * FDIM + f0 + wrow) * DMODEL + acol;
    __half* wdstbase[2];
    wdstbase[0] = (wmat ? Us[0] : Gs[0]) + wrow * SA + acol;
    wdstbase[1] = (wmat ? Us[1] : Gs[1]) + wrow * SA + acol;

    int warp = tid >> 5, lane = tid & 31;
    int wm = warp >> 1, wn = warp & 1;
    int grp = lane >> 2, tig = lane & 3;

    float accg[2][4][4]; float accu[2][4][4];
    #pragma unroll
    for (int a = 0; a < 2; a++)
        #pragma unroll
        for (int b = 0; b < 4; b++)
            #pragma unroll
            for (int c = 0; c < 4; c++) { accg[a][b][c] = 0.f; accu[a][b][c] = 0.f; }

    const int KS = DMODEL / 64;  // 16

    // prologue: stage 0
    {
        __half* ad = As[0] + arow * SA + acol;
        cp16(ad, axsrc); cp16(ad + 8, axsrc + 8); cp16(ad + 16, axsrc + 16); cp16(ad + 24, axsrc + 24);
        __half* wd = wdstbase[0];
        cp16(wd, wsrc); cp16(wd + 8, wsrc + 8); cp16(wd + 16, wsrc + 16); cp16(wd + 24, wsrc + 24);
        cp_commit();
    }

    for (int ks = 0; ks < KS; ks++) {
        if (ks + 1 < KS) {
            int st = (ks + 1) & 1, k0 = (ks + 1) * 64;
            __half* ad = As[st] + arow * SA + acol;
            const __half* a_s = axsrc + k0;
            cp16(ad, a_s); cp16(ad + 8, a_s + 8); cp16(ad + 16, a_s + 16); cp16(ad + 24, a_s + 24);
            __half* wd = wdstbase[st];
            const __half* w_s = wsrc + k0;
            cp16(wd, w_s); cp16(wd + 8, w_s + 8); cp16(wd + 16, w_s + 16); cp16(wd + 24, w_s + 24);
            cp_commit();
            asm volatile("cp.async.wait_group 1;\n" ::: "memory");
        } else {
            asm volatile("cp.async.wait_group 0;\n" ::: "memory");
        }
        __syncthreads();
        __half* A = As[ks & 1]; __half* G = Gs[ks & 1]; __half* U = Us[ks & 1];
        #pragma unroll
        for (int kk = 0; kk < 4; kk++) {
            uint32_t a[2][4];
            #pragma unroll
            for (int mi = 0; mi < 2; mi++) {
                const __half* p = A + (wm * 32 + mi * 16 + grp) * SA + kk * 16 + tig * 2;
                a[mi][0] = *(const uint32_t*)p;
                a[mi][1] = *(const uint32_t*)(p + 8 * SA);
                a[mi][2] = *(const uint32_t*)(p + 8);
                a[mi][3] = *(const uint32_t*)(p + 8 * SA + 8);
            }
            #pragma unroll
            for (int ni = 0; ni < 4; ni++) {
                int n = wn * 32 + ni * 8 + grp;
                const __half* pg = G + n * SA + kk * 16 + tig * 2;
                uint32_t bg[2] = { *(const uint32_t*)pg, *(const uint32_t*)(pg + 8) };
                const __half* pu = U + n * SA + kk * 16 + tig * 2;
                uint32_t bu[2] = { *(const uint32_t*)pu, *(const uint32_t*)(pu + 8) };
                #pragma unroll
                for (int mi = 0; mi < 2; mi++) {
                    mma16816(accg[mi][ni], a[mi], bg);
                    mma16816(accu[mi][ni], a[mi], bu);
                }
            }
        }
        __syncthreads();
    }

    int valid = s_valid;
    #pragma unroll
    for (int mi = 0; mi < 2; mi++)
        #pragma unroll
        for (int ni = 0; ni < 4; ni++) {
            int rbase = wm * 32 + mi * 16 + grp;
            int col = wn * 32 + ni * 8 + tig * 2;
            #pragma unroll
            for (int h = 0; h < 2; h++) {
                int r = rbase + h * 8;
                if (r < valid) {
                    float gg0 = accg[mi][ni][h * 2 + 0], gg1 = accg[mi][ni][h * 2 + 1];
                    float uu0 = accu[mi][ni][h * 2 + 0], uu1 = accu[mi][ni][h * 2 + 1];
                    float h0 = gg0 / (1.f + __expf(-gg0)) * uu0;
                    float h1 = gg1 / (1.f + __expf(-gg1)) * uu1;
                    *(__half2*)&g_H[(size_t)(m0 + r) * FDIM + f0 + col] = __floats2half2_rn(h0, h1);
                }
            }
        }
}

// GEMM2: O2[rows, D] = H Wd^T grouped. Tile 128 x 128, BK=64, warps 4x2 (warp tile 32x64).
__global__ __launch_bounds__(256) void k_gemm2() {
    extern __shared__ __half smem[];
    const int SA = 80;
    __half* As[2]; __half* Bs[2];
    As[0] = smem;                 Bs[0] = As[0] + 128 * SA;
    As[1] = Bs[0] + 128 * SA;     Bs[1] = As[1] + 128 * SA;

    int bx = blockIdx.x;
    if (bx >= g_ntiles[0]) return;

    __shared__ int s_e, s_m0, s_valid;
    int tid = threadIdx.x;
    if (tid == 0) {
        int e = 0;
        while (!(bx >= g_toff[e] && bx < g_toff[e + 1])) e++;
        int lt = bx - g_toff[e];
        s_e = e;
        s_m0 = g_off[e] + lt * 128;
        int cnt = g_off[e + 1] - g_off[e];
        s_valid = min(128, cnt - lt * 128);
    }
    __syncthreads();
    int e = s_e, m0 = s_m0;
    int n0 = blockIdx.y * 128;

    int row = tid >> 1;
    int coff = (tid & 1) * 32;
    const __half* asrc = g_H + (size_t)(m0 + row) * FDIM + coff;
    const __half* bsrc = g_Wd + ((size_t)e * DMODEL + n0 + row) * FDIM + coff;

    int warp = tid >> 5, lane = tid & 31;
    int wm = warp >> 1, wn = warp & 1;
    int grp = lane >> 2, tig = lane & 3;

    float acc[2][8][4];
    #pragma unroll
    for (int a = 0; a < 2; a++)
        #pragma unroll
        for (int b = 0; b < 8; b++)
            #pragma unroll
            for (int c = 0; c < 4; c++) acc[a][b][c] = 0.f;

    const int KS = FDIM / 64;  // 12

    {
        __half* ad = As[0] + row * SA + coff;
        cp16(ad, asrc); cp16(ad + 8, asrc + 8); cp16(ad + 16, asrc + 16); cp16(ad + 24, asrc + 24);
        __half* bd = Bs[0] + row * SA + coff;
        cp16(bd, bsrc); cp16(bd + 8, bsrc + 8); cp16(bd + 16, bsrc + 16); cp16(bd + 24, bsrc + 24);
        cp_commit();
    }

    for (int ks = 0; ks < KS; ks++) {
        if (ks + 1 < KS) {
            int st = (ks + 1) & 1, k0 = (ks + 1) * 64;
            __half* ad = As[st] + row * SA + coff;
            const __half* a_s = asrc + k0;
            cp16(ad, a_s); cp16(ad + 8, a_s + 8); cp16(ad + 16, a_s + 16); cp16(ad + 24, a_s + 24);
            __half* bd = Bs[st] + row * SA + coff;
            const __half* b_s = bsrc + k0;
            cp16(bd, b_s); cp16(bd + 8, b_s + 8); cp16(bd + 16, b_s + 16); cp16(bd + 24, b_s + 24);
            cp_commit();
            asm volatile("cp.async.wait_group 1;\n" ::: "memory");
        } else {
            asm volatile("cp.async.wait_group 0;\n" ::: "memory");
        }
        __syncthreads();
        __half* A = As[ks & 1]; __half* B = Bs[ks & 1];
        #pragma unroll
        for (int kk = 0; kk < 4; kk++) {
            uint32_t a[2][4];
            #pragma unroll
            for (int mi = 0; mi < 2; mi++) {
                const __half* p = A + (wm * 32 + mi * 16 + grp) * SA + kk * 16 + tig * 2;
                a[mi][0] = *(const uint32_t*)p;
                a[mi][1] = *(const uint32_t*)(p + 8 * SA);
                a[mi][2] = *(const uint32_t*)(p + 8);
                a[mi][3] = *(const uint32_t*)(p + 8 * SA + 8);
            }
            #pragma unroll
            for (int ni = 0; ni < 8; ni++) {
                int n = wn * 64 + ni * 8 + grp;
                const __half* pb = B + n * SA + kk * 16 + tig * 2;
                uint32_t b[2] = { *(const uint32_t*)pb, *(const uint32_t*)(pb + 8) };
                #pragma unroll
                for (int mi = 0; mi < 2; mi++) mma16816(acc[mi][ni], a[mi], b);
            }
        }
        __syncthreads();
    }

    int valid = s_valid;
    #pragma unroll
    for (int mi = 0; mi < 2; mi++)
        #pragma unroll
        for (int ni = 0; ni < 8; ni++) {
            int rbase = wm * 32 + mi * 16 + grp;
            int col = wn * 64 + ni * 8 + tig * 2;
            #pragma unroll
            for (int h = 0; h < 2; h++) {
                int r = rbase + h * 8;
                if (r < valid) {
                    float2 v = make_float2(acc[mi][ni][h * 2 + 0], acc[mi][ni][h * 2 + 1]);
                    *(float2*)&g_O2[(size_t)(m0 + r) * DMODEL + n0 + col] = v;
                }
            }
        }
}

__global__ void k_comb(float* __restrict__ y) {
    int i = blockIdx.x * 256 + threadIdx.x;      // over T_TOK * DMODEL / 4
    int t = i >> 8;
    int d4 = (i & 255) * 4;
    float4 acc = make_float4(0.f, 0.f, 0.f, 0.f);
    #pragma unroll
    for (int k = 0; k < TOPK; k++) {
        float w = g_w[t * TOPK + k];
        int r = g_slot2row[t * TOPK + k];
        float4 v = *(const float4*)&g_O2[(size_t)r * DMODEL + d4];
        acc.x += w * v.x; acc.y += w * v.y; acc.z += w * v.z; acc.w += w * v.w;
    }
    *(float4*)(y + (size_t)t * DMODEL + d4) = acc;
}

// ---------------- launch ----------------
extern "C" void kernel_launch(void* const* d_in, const int* in_sizes, int n_in,
                              void* d_out, int out_size) {
    const float* x  = (const float*)d_in[0];
    const float* gw = (const float*)d_in[1];
    const float* wg = (const float*)d_in[2];
    const float* wu = (const float*)d_in[3];
    const float* wd = (const float*)d_in[4];
    float* y = (float*)d_out;

    cudaFuncSetAttribute(k_gemm1, cudaFuncAttributeMaxDynamicSharedMemorySize, 81920);
    cudaFuncSetAttribute(k_gemm2, cudaFuncAttributeMaxDynamicSharedMemorySize, 81920);

    k_reset<<<1, 128>>>();
    {
        size_t nx = (size_t)T_TOK * DMODEL;
        k_cvt<<<(unsigned)(nx / 1024), 256>>>(x, 0, nx);
        size_t nw = (size_t)NEXP * FDIM * DMODEL;
        k_cvt<<<(unsigned)(nw / 1024), 256>>>(wg, 1, nw);
        k_cvt<<<(unsigned)(nw / 1024), 256>>>(wu, 2, nw);
        k_cvt<<<(unsigned)(nw / 1024), 256>>>(wd, 3, nw);
    }
    k_router<<<T_TOK / 4, 256>>>(x, gw);
    k_scan<<<1, 64>>>();
    k_scatter<<<TK / 256, 256>>>();
    k_gemm1<<<dim3(MAXT, FDIM / 64), 256, 81920>>>();
    k_gemm2<<<dim3(MAXT, DMODEL / 128), 256, 81920>>>();
    k_comb<<<(T_TOK * DMODEL / 4) / 256, 256>>>(y);
}

// round 3
// speedup vs baseline: 1.1765x; 1.1765x over previous
#include <cuda_runtime.h>
#include <cuda_fp16.h>
#include <cstdint>
#include <cstddef>

#define T_TOK 4096
#define DMODEL 1024
#define FDIM 768
#define NEXP 64
#define TOPK 8
#define TK 32768
#define MAXT 320

// ---------------- scratch ----------------
__device__ __align__(16) __half g_Xh[(size_t)T_TOK * DMODEL];
__device__ __align__(16) __half g_Wg[(size_t)NEXP * FDIM * DMODEL];
__device__ __align__(16) __half g_Wu[(size_t)NEXP * FDIM * DMODEL];
__device__ __align__(16) __half g_Wd[(size_t)NEXP * DMODEL * FDIM];
__device__ __align__(16) __half g_H[(size_t)(TK + 128) * FDIM];
__device__ __align__(16) float  g_O2[(size_t)TK * DMODEL];

__device__ int   g_ids[TK];
__device__ float g_w[TK];
__device__ int   g_counts[NEXP];
__device__ int   g_cursor[NEXP];
__device__ int   g_off[NEXP + 1];
__device__ int   g_toff[NEXP + 1];
__device__ int   g_row2tok[TK + 128];
__device__ int   g_slot2row[TK];
__device__ int   g_ntiles[1];

// ---------------- helpers ----------------
__device__ __forceinline__ void mma16816(float* c, const uint32_t* a, const uint32_t* b) {
    asm volatile(
        "mma.sync.aligned.m16n8k16.row.col.f32.f16.f16.f32 "
        "{%0,%1,%2,%3}, {%4,%5,%6,%7}, {%8,%9}, {%0,%1,%2,%3};\n"
        : "+f"(c[0]), "+f"(c[1]), "+f"(c[2]), "+f"(c[3])
        : "r"(a[0]), "r"(a[1]), "r"(a[2]), "r"(a[3]), "r"(b[0]), "r"(b[1]));
}
__device__ __forceinline__ void cp16(void* dst, const void* src) {
    uint32_t d = (uint32_t)__cvta_generic_to_shared(dst);
    asm volatile("cp.async.ca.shared.global [%0], [%1], 16;\n" :: "r"(d), "l"(src));
}
__device__ __forceinline__ void cp_commit() {
    asm volatile("cp.async.commit_group;\n" ::: "memory");
}
__device__ __forceinline__ uint32_t sw128(uint32_t o) { return o ^ ((o >> 3) & 0x70); }

#define LDSM4(r0, r1, r2, r3, addr) \
    asm volatile("ldmatrix.sync.aligned.m8n8.x4.shared.b16 {%0,%1,%2,%3}, [%4];" \
                 : "=r"(r0), "=r"(r1), "=r"(r2), "=r"(r3) : "r"(addr))

// ---------------- small kernels ----------------
__global__ void k_reset() {
    int t = threadIdx.x;
    if (t < NEXP) g_counts[t] = 0;
    if (t < 128) g_row2tok[TK + t] = 0;
}

__global__ void k_cvt(const float* __restrict__ s, int which, size_t n) {
    size_t i = ((size_t)blockIdx.x * blockDim.x + threadIdx.x) * 8;
    if (i >= n) return;
    __half* d = (which == 0) ? g_Xh : (which == 1) ? g_Wg : (which == 2) ? g_Wu : g_Wd;
    float4 v0 = *(const float4*)(s + i);
    float4 v1 = *(const float4*)(s + i + 4);
    uint4 o;
    o.x = __half2_raw(__floats2half2_rn(v0.x, v0.y)).x | ((uint32_t)__half2_raw(__floats2half2_rn(v0.x, v0.y)).y << 16);
    // simpler: build via union
    __half2 h0 = __floats2half2_rn(v0.x, v0.y);
    __half2 h1 = __floats2half2_rn(v0.z, v0.w);
    __half2 h2 = __floats2half2_rn(v1.x, v1.y);
    __half2 h3 = __floats2half2_rn(v1.z, v1.w);
    o.x = *(uint32_t*)&h0; o.y = *(uint32_t*)&h1;
    o.z = *(uint32_t*)&h2; o.w = *(uint32_t*)&h3;
    *(uint4*)(d + i) = o;
}

__global__ void k_router(const float* __restrict__ x, const float* __restrict__ gw) {
    __shared__ float sx[4][DMODEL];
    __shared__ float slog[4][NEXP];
    int t0 = blockIdx.x * 4;
    for (int i = threadIdx.x; i < 4 * DMODEL; i += 256) {
        int tl = i >> 10;
        sx[tl][i & 1023] = x[(size_t)(t0 + tl) * DMODEL + (i & 1023)];
    }
    __syncthreads();
    int tl = threadIdx.x >> 6, e = threadIdx.x & 63;
    const float4* w4 = (const float4*)(gw + (size_t)e * DMODEL);
    const float4* x4 = (const float4*)sx[tl];
    float s = 0.f;
    #pragma unroll 8
    for (int k = 0; k < DMODEL / 4; k++) {
        float4 a = x4[k], b = w4[k];
        s += a.x * b.x + a.y * b.y + a.z * b.z + a.w * b.w;
    }
    slog[tl][e] = s;
    __syncthreads();
    if (threadIdx.x < 4) {
        int t = t0 + threadIdx.x;
        float* lg = slog[threadIdx.x];
        float mx = -1e30f;
        for (int i = 0; i < NEXP; i++) mx = fmaxf(mx, lg[i]);
        float p[NEXP]; float sum = 0.f;
        for (int i = 0; i < NEXP; i++) { p[i] = __expf(lg[i] - mx); sum += p[i]; }
        float inv = 1.f / sum;
        float wsum = 0.f;
        for (int k = 0; k < TOPK; k++) {
            float best = -1.f; int bi = 0;
            for (int i = 0; i < NEXP; i++) if (p[i] > best) { best = p[i]; bi = i; }
            p[bi] = -2.f;
            float wv = best * inv;
            g_w[t * TOPK + k] = wv;
            g_ids[t * TOPK + k] = bi;
            wsum += wv;
            atomicAdd(&g_counts[bi], 1);
        }
        float rn = 1.f / (wsum + 1e-20f);
        for (int k = 0; k < TOPK; k++) g_w[t * TOPK + k] *= rn;
    }
}

__global__ void k_scan() {
    if (threadIdx.x < NEXP) g_cursor[threadIdx.x] = 0;
    if (threadIdx.x == 0) {
        int off = 0, toff = 0;
        for (int e = 0; e < NEXP; e++) {
            g_off[e] = off; g_toff[e] = toff;
            off += g_counts[e];
            toff += (g_counts[e] + 127) >> 7;
        }
        g_off[NEXP] = off; g_toff[NEXP] = toff;
        g_ntiles[0] = toff;
    }
}

__global__ void k_scatter() {
    int i = blockIdx.x * 256 + threadIdx.x;
    if (i >= TK) return;
    int e = g_ids[i];
    int p = g_off[e] + atomicAdd(&g_cursor[e], 1);
    g_row2tok[p] = i >> 3;
    g_slot2row[i] = p;
}

// ---------------- GEMM1 + SwiGLU (mma.sync + ldmatrix, 3-stage) ----------------
// grid (12, MAXT): blockIdx.x = f-block (fast -> A tile L2 reuse), blockIdx.y = row tile.
// Tile: 128 rows x 64 F for each of G,U. BK=64. Stage = A 16K + G 8K + U 8K = 32KB.
#define STAGES 3
#define STG1 32768

__global__ __launch_bounds__(256) void k_gemm1() {
    extern __shared__ char smem[];
    uint32_t sb = (uint32_t)__cvta_generic_to_shared(smem);
    int tid = threadIdx.x;
    int by = blockIdx.y;
    if (by >= g_ntiles[0]) return;

    __shared__ int s_e, s_m0, s_valid;
    __shared__ int stok[128];
    if (tid == 0) {
        int e = 0;
        while (!(by >= g_toff[e] && by < g_toff[e + 1])) e++;
        int lt = by - g_toff[e];
        s_e = e;
        s_m0 = g_off[e] + lt * 128;
        s_valid = min(128, (g_off[e + 1] - g_off[e]) - lt * 128);
    }
    __syncthreads();
    int e = s_e, m0 = s_m0;
    if (tid < 128) stok[tid] = g_row2tok[m0 + tid];
    __syncthreads();

    int f0 = blockIdx.x * 64;
    // cp.async source/dest mapping
    int arow = tid >> 1;
    int cb = (tid & 1) * 64;
    const __half* asrc = g_Xh + (size_t)stok[arow] * DMODEL + (cb >> 1);
    int wh = tid >> 7;
    int wrow = (tid & 127) >> 1;
    const __half* wsrc = (wh ? g_Wu : g_Wg) + ((size_t)e * FDIM + f0 + wrow) * DMODEL + (cb >> 1);
    uint32_t a_off = (uint32_t)arow * 128 + cb;
    uint32_t w_off = 16384 + (uint32_t)wh * 8192 + (uint32_t)wrow * 128 + cb;

    int warp = tid >> 5, lane = tid & 31;
    int wm = warp >> 1, wn = warp & 1;
    int grp = lane >> 2, tig = lane & 3;

    // ldmatrix per-lane address components
    uint32_t aRow = (uint32_t)(lane & 15);
    uint32_t aKb  = (uint32_t)(lane >> 4) * 16;
    uint32_t bRow = (uint32_t)((lane & 7) + ((lane >> 4) * 8));
    uint32_t bKb  = (uint32_t)((lane >> 3) & 1) * 16;

    float accg[2][4][4], accu[2][4][4];
    #pragma unroll
    for (int a = 0; a < 2; a++)
        #pragma unroll
        for (int b = 0; b < 4; b++)
            #pragma unroll
            for (int c = 0; c < 4; c++) { accg[a][b][c] = 0.f; accu[a][b][c] = 0.f; }

    const int KS = DMODEL / 64;   // 16
    char* tiles = smem;

    // prologue: chunks 0,1
    #pragma unroll
    for (int p = 0; p < 2; p++) {
        char* st = tiles + p * STG1;
        const __half* a_s = asrc + p * 64;
        const __half* w_s = wsrc + p * 64;
        #pragma unroll
        for (int j = 0; j < 4; j++) cp16(st + sw128(a_off + j * 16), a_s + j * 8);
        #pragma unroll
        for (int j = 0; j < 4; j++) cp16(st + sw128(w_off + j * 16), w_s + j * 8);
        cp_commit();
    }

    for (int ks = 0; ks < KS; ks++) {
        if (ks + 1 < KS) { asm volatile("cp.async.wait_group 1;\n" ::: "memory"); }
        else             { asm volatile("cp.async.wait_group 0;\n" ::: "memory"); }
        __syncthreads();
        if (ks + 2 < KS) {
            char* st = tiles + ((ks + 2) % STAGES) * STG1;
            const __half* a_s = asrc + (ks + 2) * 64;
            const __half* w_s = wsrc + (ks + 2) * 64;
            #pragma unroll
            for (int j = 0; j < 4; j++) cp16(st + sw128(a_off + j * 16), a_s + j * 8);
            #pragma unroll
            for (int j = 0; j < 4; j++) cp16(st + sw128(w_off + j * 16), w_s + j * 8);
            cp_commit();
        }
        uint32_t stg = sb + (ks % STAGES) * STG1;
        #pragma unroll
        for (int kk = 0; kk < 4; kk++) {
            uint32_t a[2][4];
            #pragma unroll
            for (int mi = 0; mi < 2; mi++) {
                uint32_t off = (uint32_t)(wm * 32 + mi * 16 + aRow) * 128 + kk * 32 + aKb;
                LDSM4(a[mi][0], a[mi][1], a[mi][2], a[mi][3], stg + sw128(off));
            }
            uint32_t bg[4][2], bu[4][2];
            #pragma unroll
            for (int h = 0; h < 2; h++) {
                uint32_t off = 16384 + (uint32_t)(wn * 32 + h * 16 + bRow) * 128 + kk * 32 + bKb;
                LDSM4(bg[h * 2][0], bg[h * 2][1], bg[h * 2 + 1][0], bg[h * 2 + 1][1], stg + sw128(off));
                uint32_t offu = off + 8192;
                LDSM4(bu[h * 2][0], bu[h * 2][1], bu[h * 2 + 1][0], bu[h * 2 + 1][1], stg + sw128(offu));
            }
            #pragma unroll
            for (int mi = 0; mi < 2; mi++)
                #pragma unroll
                for (int ng = 0; ng < 4; ng++) {
                    mma16816(accg[mi][ng], a[mi], bg[ng]);
                    mma16816(accu[mi][ng], a[mi], bu[ng]);
                }
        }
    }

    int valid = s_valid;
    #pragma unroll
    for (int mi = 0; mi < 2; mi++)
        #pragma unroll
        for (int ng = 0; ng < 4; ng++) {
            int rbase = wm * 32 + mi * 16 + grp;
            int col = wn * 32 + ng * 8 + tig * 2;
            #pragma unroll
            for (int h = 0; h < 2; h++) {
                int r = rbase + h * 8;
                if (r < valid) {
                    float g0 = accg[mi][ng][h * 2 + 0], g1 = accg[mi][ng][h * 2 + 1];
                    float u0 = accu[mi][ng][h * 2 + 0], u1 = accu[mi][ng][h * 2 + 1];
                    float h0 = g0 / (1.f + __expf(-g0)) * u0;
                    float h1 = g1 / (1.f + __expf(-g1)) * u1;
                    *(__half2*)&g_H[(size_t)(m0 + r) * FDIM + f0 + col] = __floats2half2_rn(h0, h1);
                }
            }
        }
}

// ---------------- GEMM2 (mma.sync + ldmatrix, 3-stage) ----------------
// grid (8, MAXT): blockIdx.x = n-block of 128 (fast), blockIdx.y = row tile.
// Tile 128 x 128, BK=64. Stage = A 16K + B 16K = 32KB.
#define STG2 32768

__global__ __launch_bounds__(256) void k_gemm2() {
    extern __shared__ char smem[];
    uint32_t sb = (uint32_t)__cvta_generic_to_shared(smem);
    int tid = threadIdx.x;
    int by = blockIdx.y;
    if (by >= g_ntiles[0]) return;

    __shared__ int s_e, s_m0, s_valid;
    if (tid == 0) {
        int e = 0;
        while (!(by >= g_toff[e] && by < g_toff[e + 1])) e++;
        int lt = by - g_toff[e];
        s_e = e;
        s_m0 = g_off[e] + lt * 128;
        s_valid = min(128, (g_off[e + 1] - g_off[e]) - lt * 128);
    }
    __syncthreads();
    int e = s_e, m0 = s_m0;
    int n0 = blockIdx.x * 128;

    int row = tid >> 1;
    int cb = (tid & 1) * 64;
    const __half* asrc = g_H + (size_t)(m0 + row) * FDIM + (cb >> 1);
    const __half* bsrc = g_Wd + ((size_t)e * DMODEL + n0 + row) * FDIM + (cb >> 1);
    uint32_t a_off = (uint32_t)row * 128 + cb;
    uint32_t b_off = 16384 + a_off;

    int warp = tid >> 5, lane = tid & 31;
    int wm = warp >> 1, wn = warp & 1;
    int grp = lane >> 2, tig = lane & 3;

    uint32_t aRow = (uint32_t)(lane & 15);
    uint32_t aKb  = (uint32_t)(lane >> 4) * 16;
    uint32_t bRow = (uint32_t)((lane & 7) + ((lane >> 4) * 8));
    uint32_t bKb  = (uint32_t)((lane >> 3) & 1) * 16;

    float acc[2][8][4];
    #pragma unroll
    for (int a = 0; a < 2; a++)
        #pragma unroll
        for (int b = 0; b < 8; b++)
            #pragma unroll
            for (int c = 0; c < 4; c++) acc[a][b][c] = 0.f;

    const int KS = FDIM / 64;     // 12
    char* tiles = smem;

    #pragma unroll
    for (int p = 0; p < 2; p++) {
        char* st = tiles + p * STG2;
        const __half* a_s = asrc + p * 64;
        const __half* b_s = bsrc + p * 64;
        #pragma unroll
        for (int j = 0; j < 4; j++) cp16(st + sw128(a_off + j * 16), a_s + j * 8);
        #pragma unroll
        for (int j = 0; j < 4; j++) cp16(st + sw128(b_off + j * 16), b_s + j * 8);
        cp_commit();
    }

    for (int ks = 0; ks < KS; ks++) {
        if (ks + 1 < KS) { asm volatile("cp.async.wait_group 1;\n" ::: "memory"); }
        else             { asm volatile("cp.async.wait_group 0;\n" ::: "memory"); }
        __syncthreads();
        if (ks + 2 < KS) {
            char* st = tiles + ((ks + 2) % STAGES) * STG2;
            const __half* a_s = asrc + (ks + 2) * 64;
            const __half* b_s = bsrc + (ks + 2) * 64;
            #pragma unroll
            for (int j = 0; j < 4; j++) cp16(st + sw128(a_off + j * 16), a_s + j * 8);
            #pragma unroll
            for (int j = 0; j < 4; j++) cp16(st + sw128(b_off + j * 16), b_s + j * 8);
            cp_commit();
        }
        uint32_t stg = sb + (ks % STAGES) * STG2;
        #pragma unroll
        for (int kk = 0; kk < 4; kk++) {
            uint32_t a[2][4];
            #pragma unroll
            for (int mi = 0; mi < 2; mi++) {
                uint32_t off = (uint32_t)(wm * 32 + mi * 16 + aRow) * 128 + kk * 32 + aKb;
                LDSM4(a[mi][0], a[mi][1], a[mi][2], a[mi][3], stg + sw128(off));
            }
            uint32_t b[8][2];
            #pragma unroll
            for (int h = 0; h < 4; h++) {
                uint32_t off = 16384 + (uint32_t)(wn * 64 + h * 16 + bRow) * 128 + kk * 32 + bKb;
                LDSM4(b[h * 2][0], b[h * 2][1], b[h * 2 + 1][0], b[h * 2 + 1][1], stg + sw128(off));
            }
            #pragma unroll
            for (int mi = 0; mi < 2; mi++)
                #pragma unroll
                for (int ng = 0; ng < 8; ng++)
                    mma16816(acc[mi][ng], a[mi], b[ng]);
        }
    }

    int valid = s_valid;
    #pragma unroll
    for (int mi = 0; mi < 2; mi++)
        #pragma unroll
        for (int ng = 0; ng < 8; ng++) {
            int rbase = wm * 32 + mi * 16 + grp;
            int col = wn * 64 + ng * 8 + tig * 2;
            #pragma unroll
            for (int h = 0; h < 2; h++) {
                int r = rbase + h * 8;
                if (r < valid) {
                    float2 v = make_float2(acc[mi][ng][h * 2 + 0], acc[mi][ng][h * 2 + 1]);
                    *(float2*)&g_O2[(size_t)(m0 + r) * DMODEL + n0 + col] = v;
                }
            }
        }
}

__global__ void k_comb(float* __restrict__ y) {
    int i = blockIdx.x * 256 + threadIdx.x;
    int t = i >> 8;
    int d4 = (i & 255) * 4;
    float4 acc = make_float4(0.f, 0.f, 0.f, 0.f);
    #pragma unroll
    for (int k = 0; k < TOPK; k++) {
        float w = g_w[t * TOPK + k];
        int r = g_slot2row[t * TOPK + k];
        float4 v = *(const float4*)&g_O2[(size_t)r * DMODEL + d4];
        acc.x += w * v.x; acc.y += w * v.y; acc.z += w * v.z; acc.w += w * v.w;
    }
    *(float4*)(y + (size_t)t * DMODEL + d4) = acc;
}

// ---------------- launch ----------------
extern "C" void kernel_launch(void* const* d_in, const int* in_sizes, int n_in,
                              void* d_out, int out_size) {
    const float* x  = (const float*)d_in[0];
    const float* gw = (const float*)d_in[1];
    const float* wg = (const float*)d_in[2];
    const float* wu = (const float*)d_in[3];
    const float* wd = (const float*)d_in[4];
    float* y = (float*)d_out;

    const int SMEM = STAGES * 32768;   // 98304
    cudaFuncSetAttribute(k_gemm1, cudaFuncAttributeMaxDynamicSharedMemorySize, SMEM);
    cudaFuncSetAttribute(k_gemm2, cudaFuncAttributeMaxDynamicSharedMemorySize, SMEM);

    k_reset<<<1, 128>>>();
    {
        size_t nx = (size_t)T_TOK * DMODEL;
        k_cvt<<<(unsigned)(nx / 2048), 256>>>(x, 0, nx);
        size_t nw = (size_t)NEXP * FDIM * DMODEL;
        k_cvt<<<(unsigned)(nw / 2048), 256>>>(wg, 1, nw);
        k_cvt<<<(unsigned)(nw / 2048), 256>>>(wu, 2, nw);
        k_cvt<<<(unsigned)(nw / 2048), 256>>>(wd, 3, nw);
    }
    k_router<<<T_TOK / 4, 256>>>(x, gw);
    k_scan<<<1, 64>>>();
    k_scatter<<<TK / 256, 256>>>();
    k_gemm1<<<dim3(FDIM / 64, MAXT), 256, SMEM>>>();
    k_gemm2<<<dim3(DMODEL / 128, MAXT), 256, SMEM>>>();
    k_comb<<<(T_TOK * DMODEL / 4) / 256, 256>>>(y);
}